// round 3
// baseline (speedup 1.0000x reference)
#include <cuda_runtime.h>
#include <math.h>

#define C  100
#define NB 592
#define NT 512
#define WPB (NT / 32)

__device__ float g_partials[NB];

__global__ void __launch_bounds__(NT)
kl_main(const float* __restrict__ scores,
        const int* __restrict__ labels_i32,   // raw label words; dtype detected below
        int n)
{
    __shared__ __align__(16) float s_target[C * C];   // target[l][c]
    __shared__ float s_T[C];            // sum_c target*log(target) per label
    __shared__ float s_wsum[WPB];

    const int tid = threadIdx.x;

    // ---- Detect label dtype: int64 buffers have all-zero odd 32-bit words ----
    int odd_or = 0;
    #pragma unroll
    for (int i = 1; i < 64; i += 2) odd_or |= labels_i32[i];
    const bool is64 = (odd_or == 0);

    // ---- Build the per-label target table (labels only take 100 values) ----
    if (tid < C) {
        const int   l    = tid;
        const float INVN = 0.39894228040143267794f;  // 1/sqrt(2*pi), STD=1
        float Z = 0.f;
        #pragma unroll 1
        for (int c = 0; c < C; ++c) {
            float d    = (float)(c - l);
            float code = INVN * __expf(-0.5f * d * d);
            Z += __expf(code);
        }
        float logZ = __logf(Z);
        float invZ = 1.0f / Z;
        float T = 0.f;
        #pragma unroll 1
        for (int c = 0; c < C; ++c) {
            float d    = (float)(c - l);
            float code = INVN * __expf(-0.5f * d * d);
            float t    = __expf(code) * invZ;
            s_target[l * C + c] = t;
            T += t * (code - logZ);     // t * log(t)
        }
        s_T[l] = T;
    }
    __syncthreads();

    const int lane   = tid & 31;
    const int warp   = tid >> 5;
    const int gwarp  = blockIdx.x * WPB + warp;
    const int nwarps = gridDim.x * WPB;
    const bool act   = (lane < 25);     // 100 floats = 25 x float4

    float acc = 0.f;

    for (int row = gwarp; row < n; row += nwarps) {
        const float4* rp = reinterpret_cast<const float4*>(scores + (size_t)row * C);
        float4 v;
        if (act) v = rp[lane];
        else     v = make_float4(-INFINITY, -INFINITY, -INFINITY, -INFINITY);

        // row max
        float m = fmaxf(fmaxf(v.x, v.y), fmaxf(v.z, v.w));
        #pragma unroll
        for (int o = 16; o; o >>= 1)
            m = fmaxf(m, __shfl_xor_sync(0xffffffffu, m, o));

        // sum exp
        float s = 0.f;
        if (act) {
            s = __expf(v.x - m) + __expf(v.y - m)
              + __expf(v.z - m) + __expf(v.w - m);
        }
        #pragma unroll
        for (int o = 16; o; o >>= 1)
            s += __shfl_xor_sync(0xffffffffu, s, o);

        float lse = m + __logf(s);

        // label (uniform across warp -> broadcast load); safe for both dtypes
        int l = is64 ? labels_i32[2 * row] : labels_i32[row];

        // dot(target[l], scores_row)
        float dot = 0.f;
        if (act) {
            const float4* tg = reinterpret_cast<const float4*>(s_target + l * C);
            float4 t4 = tg[lane];
            dot = v.x * t4.x + v.y * t4.y + v.z * t4.z + v.w * t4.w;
        }
        #pragma unroll
        for (int o = 16; o; o >>= 1)
            dot += __shfl_xor_sync(0xffffffffu, dot, o);

        if (lane == 0)
            acc += s_T[l] - dot + lse;
    }

    if (lane == 0) s_wsum[warp] = acc;
    __syncthreads();
    if (tid == 0) {
        float b = 0.f;
        #pragma unroll
        for (int w = 0; w < WPB; ++w) b += s_wsum[w];
        g_partials[blockIdx.x] = b;
    }
}

__global__ void kl_finalize(float* __restrict__ out, int n)
{
    __shared__ double sh[256];
    double s = 0.0;
    for (int i = threadIdx.x; i < NB; i += 256)
        s += (double)g_partials[i];
    sh[threadIdx.x] = s;
    __syncthreads();
    #pragma unroll
    for (int off = 128; off; off >>= 1) {
        if (threadIdx.x < off) sh[threadIdx.x] += sh[threadIdx.x + off];
        __syncthreads();
    }
    if (threadIdx.x == 0)
        out[0] = (float)(sh[0] / (double)n);
}

extern "C" void kernel_launch(void* const* d_in, const int* in_sizes, int n_in,
                              void* d_out, int out_size)
{
    const float* scores = (const float*)d_in[0];
    const int*   labels = (const int*)d_in[1];
    int n = in_sizes[0] / C;

    kl_main<<<NB, NT>>>(scores, labels, n);
    kl_finalize<<<1, 256>>>((float*)d_out, n);
}